// round 16
// baseline (speedup 1.0000x reference)
#include <cuda_runtime.h>
#include <cuda_fp16.h>
#include <math.h>
#include <cstdint>

#define BB 4
#define TT 2048
#define DD 1024
#define HH 16
#define HDIM 64
#define MROWS (BB*TT)   // 8192
#define GK 1024

typedef __half f16;

// ---------------------------------------------------------------------------
// Scratch (device globals — no allocation allowed). fp16 planes alias floats.
// ---------------------------------------------------------------------------
__device__ float g_q[MROWS * DD];   // qh | ql (fp16 planes)
__device__ float g_k[MROWS * DD];   // kh (single plane)
__device__ float g_v[MROWS * DD];   // vth (transposed [b][dg][t], single plane)
__device__ float g_x[MROWS * DD];   // xh | xl
__device__ float g_y[MROWS * DD];   // yh (single plane)
__device__ f16   g_w[4 * DD * DD];  // Wq,Wk,Wv,Wo single fp16 planes

__device__ __forceinline__ uint32_t smem_u32(const void* p) {
    return (uint32_t)__cvta_generic_to_shared(p);
}

__device__ __forceinline__ void split1h(float v, f16& h, f16& l) {
    h = __float2half_rn(v);
    l = __float2half_rn(v - __half2float(h));
}

__device__ __forceinline__ uint32_t pack2h(float x, float y) {
    __half2 H = __floats2half2_rn(x, y);
    return *reinterpret_cast<uint32_t*>(&H);
}

__device__ __forceinline__ void mma16816h(float* c, const uint32_t* a, const uint32_t* b) {
    asm volatile(
        "mma.sync.aligned.m16n8k16.row.col.f32.f16.f16.f32 "
        "{%0,%1,%2,%3}, {%4,%5,%6,%7}, {%8,%9}, {%0,%1,%2,%3};\n"
        : "+f"(c[0]), "+f"(c[1]), "+f"(c[2]), "+f"(c[3])
        : "r"(a[0]), "r"(a[1]), "r"(a[2]), "r"(a[3]), "r"(b[0]), "r"(b[1]));
}

__device__ __forceinline__ void ldsm4(uint32_t& r0, uint32_t& r1, uint32_t& r2, uint32_t& r3,
                                      uint32_t addr) {
    asm volatile("ldmatrix.sync.aligned.m8n8.x4.shared.b16 {%0,%1,%2,%3}, [%4];\n"
                 : "=r"(r0), "=r"(r1), "=r"(r2), "=r"(r3) : "r"(addr));
}

__device__ __forceinline__ void cpa16(uint32_t saddr, const void* g) {
    asm volatile("cp.async.ca.shared.global [%0], [%1], 16;\n" :: "r"(saddr), "l"(g));
}
__device__ __forceinline__ void cpa_commit() {
    asm volatile("cp.async.commit_group;\n");
}
template <int N>
__device__ __forceinline__ void cpa_wait() {
    asm volatile("cp.async.wait_group %0;\n" :: "n"(N));
}

// ---------------------------------------------------------------------------
// Splits / converts
// ---------------------------------------------------------------------------
__global__ void splith_kernel(const float* __restrict__ src,
                              f16* __restrict__ hi, f16* __restrict__ lo, int n)
{
    int i = blockIdx.x * blockDim.x + threadIdx.x;
    if (i < n) {
        float v = src[i];
        f16 h = __float2half_rn(v);
        hi[i] = h;
        lo[i] = __float2half_rn(v - __half2float(h));
    }
}

__global__ void convh4_kernel(const float* __restrict__ s0, const float* __restrict__ s1,
                              const float* __restrict__ s2, const float* __restrict__ s3,
                              f16* __restrict__ dst, int nW)
{
    int i = blockIdx.x * blockDim.x + threadIdx.x;
    int seg = i / nW;
    int off = i - seg * nW;
    const float* s = (seg == 0) ? s0 : (seg == 1) ? s1 : (seg == 2) ? s2 : s3;
    dst[i] = __float2half_rn(s[off]);
}

// ---------------------------------------------------------------------------
// GEMM mainloop: C = (Ah [+ Al]) * Wh^T. BM=BN=128, BK=32, 256 threads,
// 3-stage cp.async pipeline, ONE __syncthreads per iteration.
// BOFFB = byte offset of the B planes from base.
// ---------------------------------------------------------------------------
#define BK 32
#define SSTR 40
#define TILEH (128 * SSTR)

#define GEMM_MAINLOOP_H(AhP, AlP, WhP, DOAL, BOFFB)                            \
    const bool doAl = (DOAL);                                                  \
    const int lr = tid >> 1;                                                   \
    const int lc = (tid & 1) * 16;                                             \
    const f16* gAh = (AhP) + (size_t)(rowBase + lr) * GK + lc;                 \
    const f16* gAl = (AlP) + (size_t)(rowBase + lr) * GK + lc;                 \
    const f16* gWh = (WhP) + (size_t)(colBase + lr) * GK + lc;                 \
    const uint32_t soff = (uint32_t)((lr * SSTR + lc) * 2);                    \
    const uint32_t sAhB = smem_u32(smg);                                       \
    const uint32_t sAlB = sAhB + 3 * TILEH * 2;                                \
    const uint32_t sBhB = sAhB + (BOFFB);                                      \
    const int lm_row = (lane & 15);                                            \
    const int lm_col = ((lane >> 4) << 3);                                     \
    float acc[4][4][4];                                                        \
    _Pragma("unroll")                                                          \
    for (int mf = 0; mf < 4; mf++)                                             \
        _Pragma("unroll")                                                      \
        for (int nf = 0; nf < 4; nf++)                                         \
            _Pragma("unroll")                                                  \
            for (int r = 0; r < 4; r++) acc[mf][nf][r] = 0.f;                  \
    const int nIter = GK / BK;                                                 \
    auto load_stage = [&](int s, int k0) {                                     \
        const uint32_t sb = (uint32_t)(s * (TILEH * 2));                       \
        cpa16(sAhB + sb + soff,      gAh + k0);                                \
        cpa16(sAhB + sb + soff + 16, gAh + k0 + 8);                            \
        if (doAl) {                                                            \
            cpa16(sAlB + sb + soff,      gAl + k0);                            \
            cpa16(sAlB + sb + soff + 16, gAl + k0 + 8);                        \
        }                                                                      \
        cpa16(sBhB + sb + soff,      gWh + k0);                                \
        cpa16(sBhB + sb + soff + 16, gWh + k0 + 8);                            \
        cpa_commit();                                                          \
    };                                                                         \
    load_stage(0, 0);                                                          \
    load_stage(1, BK);                                                         \
    int cur = 0;                                                               \
    for (int iter = 0; iter < nIter; iter++) {                                 \
        if (iter + 1 < nIter) cpa_wait<1>(); else cpa_wait<0>();               \
        __syncthreads();                                                       \
        if (iter + 2 < nIter) {                                                \
            int pf = cur + 2; if (pf >= 3) pf -= 3;                            \
            load_stage(pf, (iter + 2) * BK);                                   \
        }                                                                      \
        _Pragma("unroll")                                                      \
        for (int ks = 0; ks < BK; ks += 16) {                                  \
            uint32_t ah[4][4], al[4][4];                                       \
            _Pragma("unroll")                                                  \
            for (int mf = 0; mf < 4; mf++) {                                   \
                int roff = (warpM * 64 + mf * 16 + lm_row) * SSTR + ks + lm_col; \
                ldsm4(ah[mf][0], ah[mf][1], ah[mf][2], ah[mf][3],              \
                      sAhB + (uint32_t)((cur * TILEH + roff) * 2));            \
                if (doAl)                                                      \
                    ldsm4(al[mf][0], al[mf][1], al[mf][2], al[mf][3],          \
                          sAlB + (uint32_t)((cur * TILEH + roff) * 2));        \
            }                                                                  \
            uint32_t bh[4][2];                                                 \
            _Pragma("unroll")                                                  \
            for (int p = 0; p < 2; p++) {                                      \
                int roff = (warpN * 32 + p * 16 + lm_row) * SSTR + ks + lm_col; \
                uint32_t r0, r1, r2, r3;                                       \
                ldsm4(r0, r1, r2, r3, sBhB + (uint32_t)((cur * TILEH + roff) * 2)); \
                bh[2 * p][0] = r0; bh[2 * p + 1][0] = r1;                      \
                bh[2 * p][1] = r2; bh[2 * p + 1][1] = r3;                      \
            }                                                                  \
            _Pragma("unroll")                                                  \
            for (int mf = 0; mf < 4; mf++)                                     \
                _Pragma("unroll")                                              \
                for (int nf = 0; nf < 4; nf++) {                               \
                    mma16816h(acc[mf][nf], ah[mf], bh[nf]);                    \
                    if (doAl) mma16816h(acc[mf][nf], al[mf], bh[nf]);          \
                }                                                              \
        }                                                                      \
        if (++cur >= 3) cur = 0;                                               \
    }

// ---------------------------------------------------------------------------
// Q-projection GEMM (split-A x2) + bias + RoPE + split-fp16 q output.
// Grid (8, 64). 9 smem planes = 92160 B (>= Csm 67584), 2 CTAs/SM.
// ---------------------------------------------------------------------------
__global__ void __launch_bounds__(256) gemm_q(
    const f16* __restrict__ Ah, const f16* __restrict__ Al,
    const f16* __restrict__ Wh, const float* __restrict__ bq,
    f16* __restrict__ qh_, f16* __restrict__ ql_)
{
    extern __shared__ f16 smg[];
    const int tid  = threadIdx.x;
    const int lane = tid & 31;
    const int wid  = tid >> 5;
    const int warpM = wid >> 2;
    const int warpN = wid & 3;
    const int bx = blockIdx.x;
    const int rowBase = blockIdx.y * 128;
    const int colBase = bx * 128;

    GEMM_MAINLOOP_H(Ah, Al, Wh, true, 6 * TILEH * 2)

    __syncthreads();

    float* Csm = (float*)smg;   // [128][132] = 67584 B
    const float* biasp = bq + bx * 128;
#pragma unroll
    for (int mf = 0; mf < 4; mf++)
#pragma unroll
        for (int nf = 0; nf < 4; nf++) {
            int r0 = warpM * 64 + mf * 16 + (lane >> 2);
            int c0 = warpN * 32 + nf * 8 + (lane & 3) * 2;
            Csm[r0 * 132 + c0]           = acc[mf][nf][0] + biasp[c0];
            Csm[r0 * 132 + c0 + 1]       = acc[mf][nf][1] + biasp[c0 + 1];
            Csm[(r0 + 8) * 132 + c0]     = acc[mf][nf][2] + biasp[c0];
            Csm[(r0 + 8) * 132 + c0 + 1] = acc[mf][nf][3] + biasp[c0 + 1];
        }
    __syncthreads();

    const int t0 = rowBase & 2047;
    const float scale = 0.125f * 1.4426950408889634f;
    const float lnc = logf(10000.f) / 32.f;
    for (int idx = tid; idx < 128 * 64; idx += 256) {
        int r  = idx >> 6;
        int pp = idx & 63;
        int hl = pp >> 5, dd = pp & 31;
        int c1 = hl * 64 + dd, c2 = c1 + 32;
        float x1 = Csm[r * 132 + c1];
        float x2 = Csm[r * 132 + c2];
        float theta = expf(-(float)dd * lnc);
        float ang = (float)(t0 + r + 1) * theta;
        float s, c;
        sincosf(ang, &s, &c);
        float y1 = (x1 * c - x2 * s) * scale;
        float y2 = (x2 * c + x1 * s) * scale;
        size_t gr = (size_t)(rowBase + r) * DD + bx * 128;
        f16 hh, ll;
        split1h(y1, hh, ll); qh_[gr + c1] = hh; ql_[gr + c1] = ll;
        split1h(y2, hh, ll); qh_[gr + c2] = hh; ql_[gr + c2] = ll;
    }
}

// ---------------------------------------------------------------------------
// K/V projection GEMM (single-A): bias + (k: RoPE fp16 | v: fp16 transposed).
// Grid (16, 64): bx 0-7 -> k, 8-15 -> v.
// smem request = max(6 planes 61440, Csm 67584) = 67584 B -> 3 CTAs/SM.
// ---------------------------------------------------------------------------
__global__ void __launch_bounds__(256, 3) gemm_kv(
    const f16* __restrict__ Ah, const f16* __restrict__ Wh,
    const float* __restrict__ bk, const float* __restrict__ bv,
    f16* __restrict__ kh_, f16* __restrict__ vth_)
{
    extern __shared__ f16 smg[];
    const int tid  = threadIdx.x;
    const int lane = tid & 31;
    const int wid  = tid >> 5;
    const int warpM = wid >> 2;
    const int warpN = wid & 3;
    const int bx = blockIdx.x;
    const int rowBase = blockIdx.y * 128;
    const int colBase = bx * 128;   // into Wk|Wv concatenated (2048 rows)

    GEMM_MAINLOOP_H(Ah, Ah, Wh, false, 3 * TILEH * 2)

    __syncthreads();

    float* Csm = (float*)smg;   // [128][132] = 67584 B (covered by smem request)
    const float* biasp = (bx < 8) ? (bk + bx * 128) : (bv + (bx - 8) * 128);
#pragma unroll
    for (int mf = 0; mf < 4; mf++)
#pragma unroll
        for (int nf = 0; nf < 4; nf++) {
            int r0 = warpM * 64 + mf * 16 + (lane >> 2);
            int c0 = warpN * 32 + nf * 8 + (lane & 3) * 2;
            Csm[r0 * 132 + c0]           = acc[mf][nf][0] + biasp[c0];
            Csm[r0 * 132 + c0 + 1]       = acc[mf][nf][1] + biasp[c0 + 1];
            Csm[(r0 + 8) * 132 + c0]     = acc[mf][nf][2] + biasp[c0];
            Csm[(r0 + 8) * 132 + c0 + 1] = acc[mf][nf][3] + biasp[c0 + 1];
        }
    __syncthreads();

    const int bB = rowBase >> 11;
    const int t0 = rowBase & 2047;

    if (bx < 8) {
        // k: RoPE + single fp16
        const int colB = bx * 128;
        const float lnc = logf(10000.f) / 32.f;
        for (int idx = tid; idx < 128 * 64; idx += 256) {
            int r  = idx >> 6;
            int pp = idx & 63;
            int hl = pp >> 5, dd = pp & 31;
            int c1 = hl * 64 + dd, c2 = c1 + 32;
            float x1 = Csm[r * 132 + c1];
            float x2 = Csm[r * 132 + c2];
            float theta = expf(-(float)dd * lnc);
            float ang = (float)(t0 + r + 1) * theta;
            float s, c;
            sincosf(ang, &s, &c);
            size_t gr = (size_t)(rowBase + r) * DD + colB;
            kh_[gr + c1] = __float2half_rn(x1 * c - x2 * s);
            kh_[gr + c2] = __float2half_rn(x2 * c + x1 * s);
        }
    } else {
        // v: single fp16, transposed store vt[b][dg][t]
        const int cb = bx - 8;
#pragma unroll
        for (int pass = 0; pass < 4; pass++) {
            int c  = pass * 32 + (wid << 2) + (lane >> 3);
            int rb = (lane & 7) * 16;
            __align__(16) f16 bh2[16];
#pragma unroll
            for (int i = 0; i < 16; i++)
                bh2[i] = __float2half_rn(Csm[(rb + i) * 132 + c]);
            size_t vb = ((size_t)bB * DD + cb * 128 + c) * TT + t0 + rb;
            *(uint4*)(vth_ + vb)     = *(uint4*)&bh2[0];
            *(uint4*)(vth_ + vb + 8) = *(uint4*)&bh2[8];
        }
    }
}

// ---------------------------------------------------------------------------
// Output-projection GEMM: C = Yh Wo^T + bias, fp32 out (single-plane A).
// No Csm stage: 6 planes = 61440 B, 3 CTAs/SM.
// ---------------------------------------------------------------------------
__global__ void __launch_bounds__(256, 3) gemm_out(
    const f16* __restrict__ Ah, const f16* __restrict__ Wh,
    const float* __restrict__ bias, float* __restrict__ C)
{
    extern __shared__ f16 smg[];
    const int tid  = threadIdx.x;
    const int lane = tid & 31;
    const int wid  = tid >> 5;
    const int warpM = wid >> 2;
    const int warpN = wid & 3;
    const int rowBase = blockIdx.y * 128;
    const int colBase = blockIdx.x * 128;

    GEMM_MAINLOOP_H(Ah, Ah, Wh, false, 3 * TILEH * 2)

#pragma unroll
    for (int mf = 0; mf < 4; mf++)
#pragma unroll
        for (int nf = 0; nf < 4; nf++) {
            int m0 = rowBase + warpM * 64 + mf * 16 + (lane >> 2);
            int n0 = colBase + warpN * 32 + nf * 8 + (lane & 3) * 2;
            float b0 = bias[n0], b1 = bias[n0 + 1];
            float2 o0 = make_float2(acc[mf][nf][0] + b0, acc[mf][nf][1] + b1);
            float2 o1 = make_float2(acc[mf][nf][2] + b0, acc[mf][nf][3] + b1);
            *(float2*)&C[(size_t)m0 * DD + n0]       = o0;
            *(float2*)&C[(size_t)(m0 + 8) * DD + n0] = o1;
        }
}

// ---------------------------------------------------------------------------
// Flash attention (round-11/14 best): 128 threads / 64 Q-rows, 4 CTAs/SM.
// 2-stage double buffer. S = (Qh+Ql) K^T (2 mmas, log2 domain), exp2f
// softmax, P·V single-plane. Buffer (18432 B): Kh | Vh, 64 x 144 B.
// ---------------------------------------------------------------------------
#define AROW 144
#define APLANE (64 * AROW)
#define ABUF (2 * APLANE)

__global__ void __launch_bounds__(128, 4) attn_mma(
    const f16* __restrict__ Qh, const f16* __restrict__ Ql,
    const f16* __restrict__ Kh, const f16* __restrict__ Vth,
    f16* __restrict__ Yh)
{
    extern __shared__ f16 asmem[];
    const uint32_t smA = smem_u32(asmem);

    const int tid  = threadIdx.x;
    const int lane = tid & 31;
    const int wid  = tid >> 5;
    const int g    = lane >> 2;
    const int t    = lane & 3;
    const int lm_row = lane & 15;
    const int lm_col = (lane >> 4) << 3;

    const int qb = (gridDim.x - 1) - blockIdx.x;
    const int bh = blockIdx.y;
    const int b  = bh >> 4;
    const int h  = bh & 15;

    const size_t headBase = (size_t)b * TT * DD + h * HDIM;
    const size_t kRow = (size_t)b * TT;
    const size_t vRow = (size_t)b * DD + h * HDIM;
    const int rowA = qb * 64 + wid * 16 + g;

    uint32_t qh[4][4], ql[4][4];
#pragma unroll
    for (int kf = 0; kf < 4; kf++) {
        int c0 = kf * 16 + 2 * t;
        size_t o00 = headBase + (size_t)rowA * DD + c0;
        size_t o10 = headBase + (size_t)(rowA + 8) * DD + c0;
        qh[kf][0] = *(const uint32_t*)(Qh + o00);
        qh[kf][1] = *(const uint32_t*)(Qh + o10);
        qh[kf][2] = *(const uint32_t*)(Qh + o00 + 8);
        qh[kf][3] = *(const uint32_t*)(Qh + o10 + 8);
        ql[kf][0] = *(const uint32_t*)(Ql + o00);
        ql[kf][1] = *(const uint32_t*)(Ql + o10);
        ql[kf][2] = *(const uint32_t*)(Ql + o00 + 8);
        ql[kf][3] = *(const uint32_t*)(Ql + o10 + 8);
    }

    float oa[8][4];
#pragma unroll
    for (int df = 0; df < 8; df++)
#pragma unroll
        for (int r = 0; r < 4; r++) oa[df][r] = 0.f;
    float m0 = -1e30f, m1 = -1e30f, l0 = 0.f, l1 = 0.f;

    const int lrow = tid >> 3;
    const int lch  = tid & 7;

    auto load_tile = [&](int jt, int bsel) {
        const uint32_t bufB = smA + (uint32_t)bsel * ABUF;
#pragma unroll
        for (int i = 0; i < 4; i++) {
            int row = lrow + i * 16;
            uint32_t sm_off = (uint32_t)(row * AROW + lch * 16);
            size_t gk = (kRow + jt * 64 + row) * DD + h * HDIM + lch * 8;
            cpa16(bufB + sm_off,          Kh + gk);
            size_t gv = (vRow + row) * TT + jt * 64 + lch * 8;
            cpa16(bufB + APLANE + sm_off, Vth + gv);
        }
        cpa_commit();
    };

    const int nTiles = qb + 1;
    load_tile(0, 0);

    for (int jt = 0; jt < nTiles; jt++) {
        const uint32_t bufB = smA + (uint32_t)(jt & 1) * ABUF;

        if (jt + 1 < nTiles) {
            load_tile(jt + 1, (jt + 1) & 1);
            cpa_wait<1>();
        } else {
            cpa_wait<0>();
        }
        __syncthreads();

        float sa[8][4];
#pragma unroll
        for (int nf = 0; nf < 8; nf++)
#pragma unroll
            for (int r = 0; r < 4; r++) sa[nf][r] = 0.f;

#pragma unroll
        for (int kf = 0; kf < 4; kf++) {
            uint32_t kbh[8][2];
#pragma unroll
            for (int p = 0; p < 4; p++) {
                uint32_t r0, r1, r2, r3;
                uint32_t ro = (uint32_t)((p * 16 + lm_row) * AROW + (kf * 16 + lm_col) * 2);
                ldsm4(r0, r1, r2, r3, bufB + ro);
                kbh[2 * p][0] = r0; kbh[2 * p + 1][0] = r1;
                kbh[2 * p][1] = r2; kbh[2 * p + 1][1] = r3;
            }
#pragma unroll
            for (int nf = 0; nf < 8; nf++) {
                mma16816h(sa[nf], qh[kf], kbh[nf]);
                mma16816h(sa[nf], ql[kf], kbh[nf]);
            }
        }

        if (jt == qb) {
#pragma unroll
            for (int nf = 0; nf < 8; nf++) {
                int col = jt * 64 + nf * 8 + 2 * t;
                if (col > rowA)         sa[nf][0] = -1e30f;
                if (col + 1 > rowA)     sa[nf][1] = -1e30f;
                if (col > rowA + 8)     sa[nf][2] = -1e30f;
                if (col + 1 > rowA + 8) sa[nf][3] = -1e30f;
            }
        }

        float mx0 = -1e30f, mx1 = -1e30f;
#pragma unroll
        for (int nf = 0; nf < 8; nf++) {
            mx0 = fmaxf(mx0, fmaxf(sa[nf][0], sa[nf][1]));
            mx1 = fmaxf(mx1, fmaxf(sa[nf][2], sa[nf][3]));
        }
        mx0 = fmaxf(mx0, __shfl_xor_sync(0xffffffffu, mx0, 1));
        mx0 = fmaxf(mx0, __shfl_xor_sync(0xffffffffu, mx0, 2));
        mx1 = fmaxf(mx1, __shfl_xor_sync(0xffffffffu, mx1, 1));
        mx1 = fmaxf(mx1, __shfl_xor_sync(0xffffffffu, mx1, 2));
        float mn0 = fmaxf(m0, mx0);
        float mn1 = fmaxf(m1, mx1);
        float al0 = exp2f(m0 - mn0);
        float al1 = exp2f(m1 - mn1);

        float sum0 = 0.f, sum1 = 0.f;
#pragma unroll
        for (int nf = 0; nf < 8; nf++) {
            sa[nf][0] = exp2f(sa[nf][0] - mn0);
            sa[nf][1] = exp2f(sa[nf][1] - mn0);
            sa[nf][2] = exp2f(sa[nf][2] - mn1);
            sa[nf][3] = exp2f(sa[nf][3] - mn1);
            sum0 += sa[nf][0] + sa[nf][1];
            sum1 += sa[nf][2] + sa[nf][3];
        }
        sum0 += __shfl_xor_sync(0xffffffffu, sum0, 1);
        sum0 += __shfl_xor_sync(0xffffffffu, sum0, 2);
        sum1 += __shfl_xor_sync(0xffffffffu, sum1, 1);
        sum1 += __shfl_xor_sync(0xffffffffu, sum1, 2);
        l0 = l0 * al0 + sum0;
        l1 = l1 * al1 + sum1;
        m0 = mn0; m1 = mn1;
#pragma unroll
        for (int df = 0; df < 8; df++) {
            oa[df][0] *= al0; oa[df][1] *= al0;
            oa[df][2] *= al1; oa[df][3] *= al1;
        }

#pragma unroll
        for (int kk = 0; kk < 4; kk++) {
            uint32_t pha[4];
            pha[0] = pack2h(sa[2 * kk][0],     sa[2 * kk][1]);
            pha[1] = pack2h(sa[2 * kk][2],     sa[2 * kk][3]);
            pha[2] = pack2h(sa[2 * kk + 1][0], sa[2 * kk + 1][1]);
            pha[3] = pack2h(sa[2 * kk + 1][2], sa[2 * kk + 1][3]);

            uint32_t vbh[8][2];
#pragma unroll
            for (int p = 0; p < 4; p++) {
                uint32_t r0, r1, r2, r3;
                uint32_t ro = (uint32_t)((p * 16 + lm_row) * AROW + (kk * 16 + lm_col) * 2);
                ldsm4(r0, r1, r2, r3, bufB + APLANE + ro);
                vbh[2 * p][0] = r0; vbh[2 * p + 1][0] = r1;
                vbh[2 * p][1] = r2; vbh[2 * p + 1][1] = r3;
            }
#pragma unroll
            for (int df = 0; df < 8; df++)
                mma16816h(oa[df], pha, vbh[df]);
        }
        __syncthreads();
    }

    float inv0 = 1.0f / l0;
    float inv1 = 1.0f / l1;
#pragma unroll
    for (int df = 0; df < 8; df++) {
        int dcol = df * 8 + 2 * t;
        size_t off0 = headBase + (size_t)rowA * DD + dcol;
        size_t off1 = headBase + (size_t)(rowA + 8) * DD + dcol;
        *(uint32_t*)&Yh[off0] = pack2h(oa[df][0] * inv0, oa[df][1] * inv0);
        *(uint32_t*)&Yh[off1] = pack2h(oa[df][2] * inv1, oa[df][3] * inv1);
    }
}

// ---------------------------------------------------------------------------
// Launch: x, Wq, bq, Wk, bk, Wv, bv, Wo, bo (all fp32)
// ---------------------------------------------------------------------------
extern "C" void kernel_launch(void* const* d_in, const int* in_sizes, int n_in,
                              void* d_out, int out_size)
{
    const float* x  = (const float*)d_in[0];
    const float* Wq = (const float*)d_in[1];
    const float* bq = (const float*)d_in[2];
    const float* Wk = (const float*)d_in[3];
    const float* bk = (const float*)d_in[4];
    const float* Wv = (const float*)d_in[5];
    const float* bv = (const float*)d_in[6];
    const float* Wo = (const float*)d_in[7];
    const float* bo = (const float*)d_in[8];
    float* out = (float*)d_out;

    float *qf, *kf, *vf, *xf, *yf;
    f16 *wp;
    cudaGetSymbolAddress((void**)&qf, g_q);
    cudaGetSymbolAddress((void**)&kf, g_k);
    cudaGetSymbolAddress((void**)&vf, g_v);
    cudaGetSymbolAddress((void**)&xf, g_x);
    cudaGetSymbolAddress((void**)&yf, g_y);
    cudaGetSymbolAddress((void**)&wp, g_w);

    const int nX = MROWS * DD;
    const int nW = DD * DD;

    f16* xh  = (f16*)xf;  f16* xl  = xh + nX;
    f16* yh  = (f16*)yf;
    f16* qh  = (f16*)qf;  f16* ql  = qh + nX;
    f16* kh  = (f16*)kf;
    f16* vth = (f16*)vf;

    splith_kernel<<<(nX + 255) / 256, 256>>>(x, xh, xl, nX);
    convh4_kernel<<<(4 * nW + 255) / 256, 256>>>(Wq, Wk, Wv, Wo, wp, nW);

    // q: 9 planes = 92160 B (>= Csm 67584), 2 CTAs/SM
    const int q_smem = 9 * TILEH * 2;
    cudaFuncSetAttribute(gemm_q, cudaFuncAttributeMaxDynamicSharedMemorySize, q_smem);
    // kv: max(6 planes 61440, Csm 67584) = 67584 B, 3 CTAs/SM (3x67584 <= 228KB)
    const int kv_smem = 128 * 132 * 4;   // 67584
    cudaFuncSetAttribute(gemm_kv, cudaFuncAttributeMaxDynamicSharedMemorySize, kv_smem);
    // out: no Csm stage -> 6 planes = 61440 B, 3 CTAs/SM
    const int out_smem = 6 * TILEH * 2;  // 61440
    cudaFuncSetAttribute(gemm_out, cudaFuncAttributeMaxDynamicSharedMemorySize, out_smem);

    const int attn_smem = 2 * ABUF;   // 36864 B
    cudaFuncSetAttribute(attn_mma, cudaFuncAttributeMaxDynamicSharedMemorySize, attn_smem);

    gemm_q<<<dim3(8, MROWS / 128), 256, q_smem>>>(xh, xl, wp, bq, qh, ql);
    // Wk|Wv are contiguous in wp (offsets 1*nW, 2*nW) -> single 2048-row B
    gemm_kv<<<dim3(16, MROWS / 128), 256, kv_smem>>>(xh, wp + 1 * nW, bk, bv, kh, vth);

    attn_mma<<<dim3(TT / 64, BB * HH), 128, attn_smem>>>(qh, ql, kh, vth, yh);

    gemm_out<<<dim3(DD / 128, MROWS / 128), 256, out_smem>>>(yh, wp + 3 * nW, bo, out);
}

// round 17
// speedup vs baseline: 1.2644x; 1.2644x over previous
#include <cuda_runtime.h>
#include <cuda_fp16.h>
#include <math.h>
#include <cstdint>

#define BB 4
#define TT 2048
#define DD 1024
#define HH 16
#define HDIM 64
#define MROWS (BB*TT)   // 8192
#define GK 1024

typedef __half f16;

// ---------------------------------------------------------------------------
// Scratch (device globals — no allocation allowed). fp16 planes alias floats.
// ---------------------------------------------------------------------------
__device__ float g_q[MROWS * DD];   // qh | ql (fp16 planes)
__device__ float g_k[MROWS * DD];   // kh (single plane)
__device__ float g_v[MROWS * DD];   // vth (transposed [b][dg][t], single plane)
__device__ float g_x[MROWS * DD];   // xh | xl
__device__ float g_y[MROWS * DD];   // yh (single plane)
__device__ f16   g_w[4 * DD * DD];  // Wq,Wk,Wv,Wo single fp16 planes

__device__ __forceinline__ uint32_t smem_u32(const void* p) {
    return (uint32_t)__cvta_generic_to_shared(p);
}

__device__ __forceinline__ void split1h(float v, f16& h, f16& l) {
    h = __float2half_rn(v);
    l = __float2half_rn(v - __half2float(h));
}

__device__ __forceinline__ uint32_t pack2h(float x, float y) {
    __half2 H = __floats2half2_rn(x, y);
    return *reinterpret_cast<uint32_t*>(&H);
}

__device__ __forceinline__ void mma16816h(float* c, const uint32_t* a, const uint32_t* b) {
    asm volatile(
        "mma.sync.aligned.m16n8k16.row.col.f32.f16.f16.f32 "
        "{%0,%1,%2,%3}, {%4,%5,%6,%7}, {%8,%9}, {%0,%1,%2,%3};\n"
        : "+f"(c[0]), "+f"(c[1]), "+f"(c[2]), "+f"(c[3])
        : "r"(a[0]), "r"(a[1]), "r"(a[2]), "r"(a[3]), "r"(b[0]), "r"(b[1]));
}

__device__ __forceinline__ void ldsm4(uint32_t& r0, uint32_t& r1, uint32_t& r2, uint32_t& r3,
                                      uint32_t addr) {
    asm volatile("ldmatrix.sync.aligned.m8n8.x4.shared.b16 {%0,%1,%2,%3}, [%4];\n"
                 : "=r"(r0), "=r"(r1), "=r"(r2), "=r"(r3) : "r"(addr));
}

__device__ __forceinline__ void cpa16(uint32_t saddr, const void* g) {
    asm volatile("cp.async.ca.shared.global [%0], [%1], 16;\n" :: "r"(saddr), "l"(g));
}
__device__ __forceinline__ void cpa_commit() {
    asm volatile("cp.async.commit_group;\n");
}
template <int N>
__device__ __forceinline__ void cpa_wait() {
    asm volatile("cp.async.wait_group %0;\n" :: "n"(N));
}

// ---------------------------------------------------------------------------
// Fused precompute: x -> (xh, xl) split AND 4 weight matrices -> fp16.
// Grid covers nX + 4*nW elements in one launch.
// ---------------------------------------------------------------------------
__global__ void prep_kernel(const float* __restrict__ x,
                            f16* __restrict__ xh, f16* __restrict__ xl,
                            const float* __restrict__ w0, const float* __restrict__ w1,
                            const float* __restrict__ w2, const float* __restrict__ w3,
                            f16* __restrict__ wdst, int nX, int nW)
{
    int i = blockIdx.x * blockDim.x + threadIdx.x;
    if (i < nX) {
        float v = x[i];
        f16 h = __float2half_rn(v);
        xh[i] = h;
        xl[i] = __float2half_rn(v - __half2float(h));
    } else {
        int j = i - nX;
        if (j < 4 * nW) {
            int seg = j / nW;
            int off = j - seg * nW;
            const float* s = (seg == 0) ? w0 : (seg == 1) ? w1 : (seg == 2) ? w2 : w3;
            wdst[j] = __float2half_rn(s[off]);
        }
    }
}

// ---------------------------------------------------------------------------
// GEMM mainloop: C = (Ah [+ Al]) * Wh^T. BM=BN=128, BK=32, 256 threads,
// 3-stage cp.async pipeline, ONE __syncthreads per iteration.
// BOFFB = byte offset of the B planes from base.
// ---------------------------------------------------------------------------
#define BK 32
#define SSTR 40
#define TILEH (128 * SSTR)

#define GEMM_MAINLOOP_H(AhP, AlP, WhP, DOAL, BOFFB)                            \
    const bool doAl = (DOAL);                                                  \
    const int lr = tid >> 1;                                                   \
    const int lc = (tid & 1) * 16;                                             \
    const f16* gAh = (AhP) + (size_t)(rowBase + lr) * GK + lc;                 \
    const f16* gAl = (AlP) + (size_t)(rowBase + lr) * GK + lc;                 \
    const f16* gWh = (WhP) + (size_t)(colBase + lr) * GK + lc;                 \
    const uint32_t soff = (uint32_t)((lr * SSTR + lc) * 2);                    \
    const uint32_t sAhB = smem_u32(smg);                                       \
    const uint32_t sAlB = sAhB + 3 * TILEH * 2;                                \
    const uint32_t sBhB = sAhB + (BOFFB);                                      \
    const int lm_row = (lane & 15);                                            \
    const int lm_col = ((lane >> 4) << 3);                                     \
    float acc[4][4][4];                                                        \
    _Pragma("unroll")                                                          \
    for (int mf = 0; mf < 4; mf++)                                             \
        _Pragma("unroll")                                                      \
        for (int nf = 0; nf < 4; nf++)                                         \
            _Pragma("unroll")                                                  \
            for (int r = 0; r < 4; r++) acc[mf][nf][r] = 0.f;                  \
    const int nIter = GK / BK;                                                 \
    auto load_stage = [&](int s, int k0) {                                     \
        const uint32_t sb = (uint32_t)(s * (TILEH * 2));                       \
        cpa16(sAhB + sb + soff,      gAh + k0);                                \
        cpa16(sAhB + sb + soff + 16, gAh + k0 + 8);                            \
        if (doAl) {                                                            \
            cpa16(sAlB + sb + soff,      gAl + k0);                            \
            cpa16(sAlB + sb + soff + 16, gAl + k0 + 8);                        \
        }                                                                      \
        cpa16(sBhB + sb + soff,      gWh + k0);                                \
        cpa16(sBhB + sb + soff + 16, gWh + k0 + 8);                            \
        cpa_commit();                                                          \
    };                                                                         \
    load_stage(0, 0);                                                          \
    load_stage(1, BK);                                                         \
    int cur = 0;                                                               \
    for (int iter = 0; iter < nIter; iter++) {                                 \
        if (iter + 1 < nIter) cpa_wait<1>(); else cpa_wait<0>();               \
        __syncthreads();                                                       \
        if (iter + 2 < nIter) {                                                \
            int pf = cur + 2; if (pf >= 3) pf -= 3;                            \
            load_stage(pf, (iter + 2) * BK);                                   \
        }                                                                      \
        _Pragma("unroll")                                                      \
        for (int ks = 0; ks < BK; ks += 16) {                                  \
            uint32_t ah[4][4], al[4][4];                                       \
            _Pragma("unroll")                                                  \
            for (int mf = 0; mf < 4; mf++) {                                   \
                int roff = (warpM * 64 + mf * 16 + lm_row) * SSTR + ks + lm_col; \
                ldsm4(ah[mf][0], ah[mf][1], ah[mf][2], ah[mf][3],              \
                      sAhB + (uint32_t)((cur * TILEH + roff) * 2));            \
                if (doAl)                                                      \
                    ldsm4(al[mf][0], al[mf][1], al[mf][2], al[mf][3],          \
                          sAlB + (uint32_t)((cur * TILEH + roff) * 2));        \
            }                                                                  \
            uint32_t bh[4][2];                                                 \
            _Pragma("unroll")                                                  \
            for (int p = 0; p < 2; p++) {                                      \
                int roff = (warpN * 32 + p * 16 + lm_row) * SSTR + ks + lm_col; \
                uint32_t r0, r1, r2, r3;                                       \
                ldsm4(r0, r1, r2, r3, sBhB + (uint32_t)((cur * TILEH + roff) * 2)); \
                bh[2 * p][0] = r0; bh[2 * p + 1][0] = r1;                      \
                bh[2 * p][1] = r2; bh[2 * p + 1][1] = r3;                      \
            }                                                                  \
            _Pragma("unroll")                                                  \
            for (int mf = 0; mf < 4; mf++)                                     \
                _Pragma("unroll")                                              \
                for (int nf = 0; nf < 4; nf++) {                               \
                    mma16816h(acc[mf][nf], ah[mf], bh[nf]);                    \
                    if (doAl) mma16816h(acc[mf][nf], al[mf], bh[nf]);          \
                }                                                              \
        }                                                                      \
        if (++cur >= 3) cur = 0;                                               \
    }

// ---------------------------------------------------------------------------
// Fused QKV GEMM + bias + RoPE + fp16 outputs (+ V transposed).
// Grid (24, 64): bx 0-7 -> q (x split x2, log2e folded into scale),
// 8-15 -> k (x single), 16-23 -> v (x single, transposed store).
// ---------------------------------------------------------------------------
__global__ void __launch_bounds__(256) gemm_qkv(
    const f16* __restrict__ Ah, const f16* __restrict__ Al,
    const f16* __restrict__ Wh,
    const float* __restrict__ bq, const float* __restrict__ bk,
    const float* __restrict__ bv,
    f16* __restrict__ qh_, f16* __restrict__ ql_,
    f16* __restrict__ kh_, f16* __restrict__ vth_)
{
    extern __shared__ f16 smg[];
    const int tid  = threadIdx.x;
    const int lane = tid & 31;
    const int wid  = tid >> 5;
    const int warpM = wid >> 2;
    const int warpN = wid & 3;
    const int bx = blockIdx.x;
    const int rowBase = blockIdx.y * 128;
    const int colBase = bx * 128;

    GEMM_MAINLOOP_H(Ah, Al, Wh, bx < 8, 6 * TILEH * 2)

    // all warps done with smem planes before Csm overwrite
    __syncthreads();

    // ---- epilogue: stage to smem fp32 with bias ----
    float* Csm = (float*)smg;   // [128][132]
    const float* biasp = (bx < 8) ? (bq + bx * 128)
                       : (bx < 16) ? (bk + (bx - 8) * 128)
                                   : (bv + (bx - 16) * 128);
#pragma unroll
    for (int mf = 0; mf < 4; mf++)
#pragma unroll
        for (int nf = 0; nf < 4; nf++) {
            int r0 = warpM * 64 + mf * 16 + (lane >> 2);
            int c0 = warpN * 32 + nf * 8 + (lane & 3) * 2;
            Csm[r0 * 132 + c0]           = acc[mf][nf][0] + biasp[c0];
            Csm[r0 * 132 + c0 + 1]       = acc[mf][nf][1] + biasp[c0 + 1];
            Csm[(r0 + 8) * 132 + c0]     = acc[mf][nf][2] + biasp[c0];
            Csm[(r0 + 8) * 132 + c0 + 1] = acc[mf][nf][3] + biasp[c0 + 1];
        }
    __syncthreads();

    const int bB = rowBase >> 11;       // batch
    const int t0 = rowBase & 2047;      // time offset within batch

    if (bx < 8) {
        // q: RoPE + scale (0.125 * log2e, softmax runs in exp2 domain) + split x2
        const int colB = bx * 128;
        const float scale = 0.125f * 1.4426950408889634f;
        const float lnc = logf(10000.f) / 32.f;
        for (int idx = tid; idx < 128 * 64; idx += 256) {
            int r  = idx >> 6;
            int pp = idx & 63;
            int hl = pp >> 5, dd = pp & 31;
            int c1 = hl * 64 + dd, c2 = c1 + 32;
            float x1 = Csm[r * 132 + c1];
            float x2 = Csm[r * 132 + c2];
            float theta = expf(-(float)dd * lnc);
            float ang = (float)(t0 + r + 1) * theta;
            float s, c;
            sincosf(ang, &s, &c);
            float y1 = (x1 * c - x2 * s) * scale;
            float y2 = (x2 * c + x1 * s) * scale;
            size_t gr = (size_t)(rowBase + r) * DD + colB;
            f16 hh, ll;
            split1h(y1, hh, ll); qh_[gr + c1] = hh; ql_[gr + c1] = ll;
            split1h(y2, hh, ll); qh_[gr + c2] = hh; ql_[gr + c2] = ll;
        }
    } else if (bx < 16) {
        // k: RoPE + single fp16
        const int colB = (bx - 8) * 128;
        const float lnc = logf(10000.f) / 32.f;
        for (int idx = tid; idx < 128 * 64; idx += 256) {
            int r  = idx >> 6;
            int pp = idx & 63;
            int hl = pp >> 5, dd = pp & 31;
            int c1 = hl * 64 + dd, c2 = c1 + 32;
            float x1 = Csm[r * 132 + c1];
            float x2 = Csm[r * 132 + c2];
            float theta = expf(-(float)dd * lnc);
            float ang = (float)(t0 + r + 1) * theta;
            float s, c;
            sincosf(ang, &s, &c);
            size_t gr = (size_t)(rowBase + r) * DD + colB;
            kh_[gr + c1] = __float2half_rn(x1 * c - x2 * s);
            kh_[gr + c2] = __float2half_rn(x2 * c + x1 * s);
        }
    } else {
        // v: single fp16, transposed store vt[b][dg][t]
        const int cb = bx - 16;
#pragma unroll
        for (int pass = 0; pass < 4; pass++) {
            int c  = pass * 32 + (wid << 2) + (lane >> 3);
            int rb = (lane & 7) * 16;
            __align__(16) f16 bh2[16];
#pragma unroll
            for (int i = 0; i < 16; i++)
                bh2[i] = __float2half_rn(Csm[(rb + i) * 132 + c]);
            size_t vb = ((size_t)bB * DD + cb * 128 + c) * TT + t0 + rb;
            *(uint4*)(vth_ + vb)     = *(uint4*)&bh2[0];
            *(uint4*)(vth_ + vb + 8) = *(uint4*)&bh2[8];
        }
    }
}

// ---------------------------------------------------------------------------
// Output-projection GEMM: C = Yh Wo^T + bias, fp32 out (single-plane A).
// B planes directly after A planes (no Al) -> 61440 B smem.
// ---------------------------------------------------------------------------
__global__ void __launch_bounds__(256) gemm_out(
    const f16* __restrict__ Ah, const f16* __restrict__ Wh,
    const float* __restrict__ bias, float* __restrict__ C)
{
    extern __shared__ f16 smg[];
    const int tid  = threadIdx.x;
    const int lane = tid & 31;
    const int wid  = tid >> 5;
    const int warpM = wid >> 2;
    const int warpN = wid & 3;
    const int rowBase = blockIdx.y * 128;
    const int colBase = blockIdx.x * 128;

    GEMM_MAINLOOP_H(Ah, Ah, Wh, false, 3 * TILEH * 2)

#pragma unroll
    for (int mf = 0; mf < 4; mf++)
#pragma unroll
        for (int nf = 0; nf < 4; nf++) {
            int m0 = rowBase + warpM * 64 + mf * 16 + (lane >> 2);
            int n0 = colBase + warpN * 32 + nf * 8 + (lane & 3) * 2;
            float b0 = bias[n0], b1 = bias[n0 + 1];
            float2 o0 = make_float2(acc[mf][nf][0] + b0, acc[mf][nf][1] + b1);
            float2 o1 = make_float2(acc[mf][nf][2] + b0, acc[mf][nf][3] + b1);
            *(float2*)&C[(size_t)m0 * DD + n0]       = o0;
            *(float2*)&C[(size_t)(m0 + 8) * DD + n0] = o1;
        }
}

// ---------------------------------------------------------------------------
// Flash attention (round-11/14 best): 128 threads / 64 Q-rows, 4 CTAs/SM.
// 2-stage double buffer. S = (Qh+Ql) K^T (2 mmas, log2 domain), exp2f
// softmax, P·V single-plane. Buffer (18432 B): Kh | Vh, 64 x 144 B.
// ---------------------------------------------------------------------------
#define AROW 144
#define APLANE (64 * AROW)
#define ABUF (2 * APLANE)

__global__ void __launch_bounds__(128, 4) attn_mma(
    const f16* __restrict__ Qh, const f16* __restrict__ Ql,
    const f16* __restrict__ Kh, const f16* __restrict__ Vth,
    f16* __restrict__ Yh)
{
    extern __shared__ f16 asmem[];
    const uint32_t smA = smem_u32(asmem);

    const int tid  = threadIdx.x;
    const int lane = tid & 31;
    const int wid  = tid >> 5;
    const int g    = lane >> 2;
    const int t    = lane & 3;
    const int lm_row = lane & 15;
    const int lm_col = (lane >> 4) << 3;

    const int qb = (gridDim.x - 1) - blockIdx.x;
    const int bh = blockIdx.y;
    const int b  = bh >> 4;
    const int h  = bh & 15;

    const size_t headBase = (size_t)b * TT * DD + h * HDIM;
    const size_t kRow = (size_t)b * TT;
    const size_t vRow = (size_t)b * DD + h * HDIM;
    const int rowA = qb * 64 + wid * 16 + g;

    uint32_t qh[4][4], ql[4][4];
#pragma unroll
    for (int kf = 0; kf < 4; kf++) {
        int c0 = kf * 16 + 2 * t;
        size_t o00 = headBase + (size_t)rowA * DD + c0;
        size_t o10 = headBase + (size_t)(rowA + 8) * DD + c0;
        qh[kf][0] = *(const uint32_t*)(Qh + o00);
        qh[kf][1] = *(const uint32_t*)(Qh + o10);
        qh[kf][2] = *(const uint32_t*)(Qh + o00 + 8);
        qh[kf][3] = *(const uint32_t*)(Qh + o10 + 8);
        ql[kf][0] = *(const uint32_t*)(Ql + o00);
        ql[kf][1] = *(const uint32_t*)(Ql + o10);
        ql[kf][2] = *(const uint32_t*)(Ql + o00 + 8);
        ql[kf][3] = *(const uint32_t*)(Ql + o10 + 8);
    }

    float oa[8][4];
#pragma unroll
    for (int df = 0; df < 8; df++)
#pragma unroll
        for (int r = 0; r < 4; r++) oa[df][r] = 0.f;
    float m0 = -1e30f, m1 = -1e30f, l0 = 0.f, l1 = 0.f;

    const int lrow = tid >> 3;
    const int lch  = tid & 7;

    auto load_tile = [&](int jt, int bsel) {
        const uint32_t bufB = smA + (uint32_t)bsel * ABUF;
#pragma unroll
        for (int i = 0; i < 4; i++) {
            int row = lrow + i * 16;
            uint32_t sm_off = (uint32_t)(row * AROW + lch * 16);
            size_t gk = (kRow + jt * 64 + row) * DD + h * HDIM + lch * 8;
            cpa16(bufB + sm_off,          Kh + gk);
            size_t gv = (vRow + row) * TT + jt * 64 + lch * 8;
            cpa16(bufB + APLANE + sm_off, Vth + gv);
        }
        cpa_commit();
    };

    const int nTiles = qb + 1;
    load_tile(0, 0);

    for (int jt = 0; jt < nTiles; jt++) {
        const uint32_t bufB = smA + (uint32_t)(jt & 1) * ABUF;

        if (jt + 1 < nTiles) {
            load_tile(jt + 1, (jt + 1) & 1);
            cpa_wait<1>();
        } else {
            cpa_wait<0>();
        }
        __syncthreads();

        float sa[8][4];
#pragma unroll
        for (int nf = 0; nf < 8; nf++)
#pragma unroll
            for (int r = 0; r < 4; r++) sa[nf][r] = 0.f;

#pragma unroll
        for (int kf = 0; kf < 4; kf++) {
            uint32_t kbh[8][2];
#pragma unroll
            for (int p = 0; p < 4; p++) {
                uint32_t r0, r1, r2, r3;
                uint32_t ro = (uint32_t)((p * 16 + lm_row) * AROW + (kf * 16 + lm_col) * 2);
                ldsm4(r0, r1, r2, r3, bufB + ro);
                kbh[2 * p][0] = r0; kbh[2 * p + 1][0] = r1;
                kbh[2 * p][1] = r2; kbh[2 * p + 1][1] = r3;
            }
#pragma unroll
            for (int nf = 0; nf < 8; nf++) {
                mma16816h(sa[nf], qh[kf], kbh[nf]);
                mma16816h(sa[nf], ql[kf], kbh[nf]);
            }
        }

        if (jt == qb) {
#pragma unroll
            for (int nf = 0; nf < 8; nf++) {
                int col = jt * 64 + nf * 8 + 2 * t;
                if (col > rowA)         sa[nf][0] = -1e30f;
                if (col + 1 > rowA)     sa[nf][1] = -1e30f;
                if (col > rowA + 8)     sa[nf][2] = -1e30f;
                if (col + 1 > rowA + 8) sa[nf][3] = -1e30f;
            }
        }

        float mx0 = -1e30f, mx1 = -1e30f;
#pragma unroll
        for (int nf = 0; nf < 8; nf++) {
            mx0 = fmaxf(mx0, fmaxf(sa[nf][0], sa[nf][1]));
            mx1 = fmaxf(mx1, fmaxf(sa[nf][2], sa[nf][3]));
        }
        mx0 = fmaxf(mx0, __shfl_xor_sync(0xffffffffu, mx0, 1));
        mx0 = fmaxf(mx0, __shfl_xor_sync(0xffffffffu, mx0, 2));
        mx1 = fmaxf(mx1, __shfl_xor_sync(0xffffffffu, mx1, 1));
        mx1 = fmaxf(mx1, __shfl_xor_sync(0xffffffffu, mx1, 2));
        float mn0 = fmaxf(m0, mx0);
        float mn1 = fmaxf(m1, mx1);
        float al0 = exp2f(m0 - mn0);
        float al1 = exp2f(m1 - mn1);

        float sum0 = 0.f, sum1 = 0.f;
#pragma unroll
        for (int nf = 0; nf < 8; nf++) {
            sa[nf][0] = exp2f(sa[nf][0] - mn0);
            sa[nf][1] = exp2f(sa[nf][1] - mn0);
            sa[nf][2] = exp2f(sa[nf][2] - mn1);
            sa[nf][3] = exp2f(sa[nf][3] - mn1);
            sum0 += sa[nf][0] + sa[nf][1];
            sum1 += sa[nf][2] + sa[nf][3];
        }
        sum0 += __shfl_xor_sync(0xffffffffu, sum0, 1);
        sum0 += __shfl_xor_sync(0xffffffffu, sum0, 2);
        sum1 += __shfl_xor_sync(0xffffffffu, sum1, 1);
        sum1 += __shfl_xor_sync(0xffffffffu, sum1, 2);
        l0 = l0 * al0 + sum0;
        l1 = l1 * al1 + sum1;
        m0 = mn0; m1 = mn1;
#pragma unroll
        for (int df = 0; df < 8; df++) {
            oa[df][0] *= al0; oa[df][1] *= al0;
            oa[df][2] *= al1; oa[df][3] *= al1;
        }

#pragma unroll
        for (int kk = 0; kk < 4; kk++) {
            uint32_t pha[4];
            pha[0] = pack2h(sa[2 * kk][0],     sa[2 * kk][1]);
            pha[1] = pack2h(sa[2 * kk][2],     sa[2 * kk][3]);
            pha[2] = pack2h(sa[2 * kk + 1][0], sa[2 * kk + 1][1]);
            pha[3] = pack2h(sa[2 * kk + 1][2], sa[2 * kk + 1][3]);

            uint32_t vbh[8][2];
#pragma unroll
            for (int p = 0; p < 4; p++) {
                uint32_t r0, r1, r2, r3;
                uint32_t ro = (uint32_t)((p * 16 + lm_row) * AROW + (kk * 16 + lm_col) * 2);
                ldsm4(r0, r1, r2, r3, bufB + APLANE + ro);
                vbh[2 * p][0] = r0; vbh[2 * p + 1][0] = r1;
                vbh[2 * p][1] = r2; vbh[2 * p + 1][1] = r3;
            }
#pragma unroll
            for (int df = 0; df < 8; df++)
                mma16816h(oa[df], pha, vbh[df]);
        }
        __syncthreads();
    }

    float inv0 = 1.0f / l0;
    float inv1 = 1.0f / l1;
#pragma unroll
    for (int df = 0; df < 8; df++) {
        int dcol = df * 8 + 2 * t;
        size_t off0 = headBase + (size_t)rowA * DD + dcol;
        size_t off1 = headBase + (size_t)(rowA + 8) * DD + dcol;
        *(uint32_t*)&Yh[off0] = pack2h(oa[df][0] * inv0, oa[df][1] * inv0);
        *(uint32_t*)&Yh[off1] = pack2h(oa[df][2] * inv1, oa[df][3] * inv1);
    }
}

// ---------------------------------------------------------------------------
// Launch: x, Wq, bq, Wk, bk, Wv, bv, Wo, bo (all fp32)
// ---------------------------------------------------------------------------
extern "C" void kernel_launch(void* const* d_in, const int* in_sizes, int n_in,
                              void* d_out, int out_size)
{
    const float* x  = (const float*)d_in[0];
    const float* Wq = (const float*)d_in[1];
    const float* bq = (const float*)d_in[2];
    const float* Wk = (const float*)d_in[3];
    const float* bk = (const float*)d_in[4];
    const float* Wv = (const float*)d_in[5];
    const float* bv = (const float*)d_in[6];
    const float* Wo = (const float*)d_in[7];
    const float* bo = (const float*)d_in[8];
    float* out = (float*)d_out;

    float *qf, *kf, *vf, *xf, *yf;
    f16 *wp;
    cudaGetSymbolAddress((void**)&qf, g_q);
    cudaGetSymbolAddress((void**)&kf, g_k);
    cudaGetSymbolAddress((void**)&vf, g_v);
    cudaGetSymbolAddress((void**)&xf, g_x);
    cudaGetSymbolAddress((void**)&yf, g_y);
    cudaGetSymbolAddress((void**)&wp, g_w);

    const int nX = MROWS * DD;
    const int nW = DD * DD;

    f16* xh  = (f16*)xf;  f16* xl  = xh + nX;
    f16* yh  = (f16*)yf;
    f16* qh  = (f16*)qf;  f16* ql  = qh + nX;
    f16* kh  = (f16*)kf;
    f16* vth = (f16*)vf;

    prep_kernel<<<(nX + 4 * nW + 255) / 256, 256>>>(
        x, xh, xl, Wq, Wk, Wv, Wo, wp, nX, nW);

    // qkv: 3 stages x (Ah + Al + B) = 9 planes = 92160 B (>= Csm 67584)
    const int qkv_smem = 9 * TILEH * 2;
    cudaFuncSetAttribute(gemm_qkv, cudaFuncAttributeMaxDynamicSharedMemorySize, qkv_smem);
    // out: 3 stages x (Ah + B) = 6 planes = 61440 B
    const int out_smem = 6 * TILEH * 2;
    cudaFuncSetAttribute(gemm_out, cudaFuncAttributeMaxDynamicSharedMemorySize, out_smem);

    const int attn_smem = 2 * ABUF;   // 36864 B
    cudaFuncSetAttribute(attn_mma, cudaFuncAttributeMaxDynamicSharedMemorySize, attn_smem);

    gemm_qkv<<<dim3(24, MROWS / 128), 256, qkv_smem>>>(
        xh, xl, wp, bq, bk, bv, qh, ql, kh, vth);

    attn_mma<<<dim3(TT / 64, BB * HH), 128, attn_smem>>>(
        qh, ql, kh, vth, yh);

    gemm_out<<<dim3(DD / 128, MROWS / 128), 256, out_smem>>>(
        yh, wp + 3 * nW, bo, out);
}